// round 17
// baseline (speedup 1.0000x reference)
#include <cuda_runtime.h>
#include <math.h>

#define NMAX  12288
#define QB    128
#define NB    888             // persistent blocks: 6/SM x 148, all co-resident
#define NCHK  (NMAX / QB)     // 96 chunks (1 point per thread)
#define SBLK  (NMAX / QB)     // 96 strain blocks
#define QW    512             // queries per window (4 per thread)
#define NQT   4               // queries per thread
#define TCAP  344             // worst-case slice (ncomp^2/(512*NB) bound) + pad

struct CMat { float m[9]; float s; };

// ---- persistent scratch (zero-init; monotone counters, no resets) ----
__device__ int    g_ccnt[NCHK];                 // per-chunk inside counts
__device__ int    g_ncomp;                      // total inside count
__device__ float4 g_cand[NMAX];                 // globally index-ordered compacted
__device__ int    g_cidx[NMAX];                 // compact slot -> original index
__device__ unsigned long long g_best[NMAX];     // per-slot ~((ord(d)<<32)|slot); 0 = armed
__device__ double g_bsum[SBLK];
__device__ int    g_bcnt[SBLK];
__device__ unsigned int g_c0, g_c1, g_c2, g_c3; // monotone barrier/ticket counters

__device__ __forceinline__ unsigned int ford(float f) {
    unsigned int u = __float_as_uint(f);
    return (u & 0x80000000u) ? ~u : (u | 0x80000000u);
}
__device__ __forceinline__ float finv(unsigned int o) {
    unsigned int u = (o & 0x80000000u) ? (o ^ 0x80000000u) : ~o;
    return __uint_as_float(u);
}

// monotone grid barrier (no reset -> no stale-spinner hazard across replays)
__device__ __forceinline__ void gbar(unsigned int* ctr) {
    __syncthreads();
    if (threadIdx.x == 0) {
        __threadfence();
        unsigned int v = atomicAdd(ctr, 1u);
        unsigned int target = (v / NB + 1u) * NB;
        while (*(volatile unsigned int*)ctr < target) __nanosleep(64);
        __threadfence();
    }
    __syncthreads();
}

// ============================================================
// One persistent kernel:
// count -> gbar -> global compact -> gbar -> NN (4q/thread) -> gbar -> strain
// ============================================================
__global__ void __launch_bounds__(QB, 6) k_all(const float* __restrict__ new_xyz,
                                               const float* __restrict__ xyz,
                                               const float* __restrict__ gt_sdf,
                                               CMat C, float* __restrict__ out) {
    __shared__ float4 tile[TCAP];         // 5.5 KB
    __shared__ int    s_w[4];
    __shared__ int    s_c[NCHK];
    __shared__ double s_rd[QB];
    __shared__ int    s_ri[QB];
    __shared__ int    s_last;

    int tid = threadIdx.x, lane = tid & 31, wid = tid >> 5;
    int b   = blockIdx.x;

    // ---------- Phase A: per-chunk counts (blocks 0..95) ----------
    if (b < NCHK) {
        int i = b * QB + tid;
        bool f = gt_sdf[i] < 1e-8f;
        unsigned bal = __ballot_sync(0xffffffffu, f);
        if (lane == 0) s_w[wid] = __popc(bal);
        __syncthreads();
        if (tid == 0) g_ccnt[b] = s_w[0] + s_w[1] + s_w[2] + s_w[3];
    }
    gbar(&g_c0);

    // ---------- Phase B: globally-ordered compaction (blocks 0..95) ----------
    if (b < NCHK) {
        if (tid < NCHK) s_c[tid] = g_ccnt[tid];
        __syncthreads();
        int base = 0, tot = 0;
        #pragma unroll 8
        for (int j = 0; j < NCHK; ++j) { int v = s_c[j]; if (j < b) base += v; tot += v; }

        int i = b * QB + tid;
        bool f = gt_sdf[i] < 1e-8f;
        unsigned bal = __ballot_sync(0xffffffffu, f);
        int pre = __popc(bal & ((1u << lane) - 1u));
        if (lane == 0) s_w[wid] = __popc(bal);
        __syncthreads();
        int woff = 0;
        #pragma unroll
        for (int w = 0; w < 4; ++w) if (w < wid) woff += s_w[w];
        if (f) {
            int pos = base + woff + pre;                  // global index-ordered slot
            float x = new_xyz[3 * i + 0];
            float y = new_xyz[3 * i + 1];
            float z = new_xyz[3 * i + 2];
            g_cand[pos] = make_float4(x, y, z, x * x + y * y + z * z);
            g_cidx[pos] = i;
        }
        if (b == 0 && tid == 0) g_ncomp = tot;
    }
    gbar(&g_c1);

    // ---------- Phase C: NN, one uniform item per block, 4 q/thread ----------
    {
        int ncomp   = g_ncomp;
        int windows = (ncomp + QW - 1) / QW;
        int S       = (windows > 0) ? (NB / windows) : 0;
        int used    = windows * S;

        if (ncomp > 0 && b < used) {
            int widx  = b % windows;
            int slice = b / windows;
            int qw0   = widx * QW;
            int lo    = (int)((long long)slice * ncomp / S);
            int hi    = (int)((long long)(slice + 1) * ncomp / S);
            int cntc  = hi - lo;

            for (int k = tid; k < cntc; k += QB)
                tile[k] = g_cand[lo + k];
            if (tid < 4)                                  // pad for batch-4
                tile[cntc + tid] = make_float4(0.f, 0.f, 0.f, 1e30f);
            __syncthreads();

            if (cntc > 0) {                               // block-uniform
                int   ql[NQT];
                bool  qa[NQT];
                float ax[NQT], ay[NQT], az[NQT];
                int   sk[NQT];
                #pragma unroll
                for (int j = 0; j < NQT; ++j) {
                    ql[j] = qw0 + j * QB + tid;
                    qa[j] = (ql[j] < ncomp);
                    float4 w = g_cand[min(ql[j], ncomp - 1)];
                    ax[j] = -2.f * w.x; ay[j] = -2.f * w.y; az[j] = -2.f * w.z;
                    sk[j] = ql[j] - lo;
                }
                bool overlap = (lo < qw0 + QW) && (hi > qw0);   // block-uniform

                int cntc4 = (cntc + 3) & ~3;
                float best[NQT] = {3.0e38f, 3.0e38f, 3.0e38f, 3.0e38f};
                int   kb[NQT]   = {0, 0, 0, 0};

                if (!overlap) {
                    for (int k = 0; k < cntc4; k += 4) {
                        float4 c0 = tile[k+0], c1 = tile[k+1];
                        float4 c2 = tile[k+2], c3 = tile[k+3];
                        #pragma unroll
                        for (int j = 0; j < NQT; ++j) {
                            float d0 = fmaf(c0.x, ax[j], fmaf(c0.y, ay[j], fmaf(c0.z, az[j], c0.w)));
                            float d1 = fmaf(c1.x, ax[j], fmaf(c1.y, ay[j], fmaf(c1.z, az[j], c1.w)));
                            float d2 = fmaf(c2.x, ax[j], fmaf(c2.y, ay[j], fmaf(c2.z, az[j], c2.w)));
                            float d3 = fmaf(c3.x, ax[j], fmaf(c3.y, ay[j], fmaf(c3.z, az[j], c3.w)));
                            float m = fminf(fminf(d0, d1), fminf(d2, d3));
                            if (m < best[j]) { best[j] = m; kb[j] = k; }
                        }
                    }
                } else {
                    for (int k = 0; k < cntc4; k += 4) {
                        float4 c0 = tile[k+0], c1 = tile[k+1];
                        float4 c2 = tile[k+2], c3 = tile[k+3];
                        bool fix = __any_sync(0xffffffffu,
                            ((unsigned)(sk[0] - k) < 4u) | ((unsigned)(sk[1] - k) < 4u) |
                            ((unsigned)(sk[2] - k) < 4u) | ((unsigned)(sk[3] - k) < 4u));
                        #pragma unroll
                        for (int j = 0; j < NQT; ++j) {
                            float d0 = fmaf(c0.x, ax[j], fmaf(c0.y, ay[j], fmaf(c0.z, az[j], c0.w)));
                            float d1 = fmaf(c1.x, ax[j], fmaf(c1.y, ay[j], fmaf(c1.z, az[j], c1.w)));
                            float d2 = fmaf(c2.x, ax[j], fmaf(c2.y, ay[j], fmaf(c2.z, az[j], c2.w)));
                            float d3 = fmaf(c3.x, ax[j], fmaf(c3.y, ay[j], fmaf(c3.z, az[j], c3.w)));
                            if (fix) {                    // rare: self in this batch
                                d0 = (k + 0 == sk[j]) ? 3e38f : d0;
                                d1 = (k + 1 == sk[j]) ? 3e38f : d1;
                                d2 = (k + 2 == sk[j]) ? 3e38f : d2;
                                d3 = (k + 3 == sk[j]) ? 3e38f : d3;
                            }
                            float m = fminf(fminf(d0, d1), fminf(d2, d3));
                            if (m < best[j]) { best[j] = m; kb[j] = k; }
                        }
                    }
                }

                // recovery: first element of winning batch with d == best
                #pragma unroll
                for (int j = 0; j < NQT; ++j) {
                    if (!qa[j]) continue;
                    int bi = kb[j]; bool found = false;
                    #pragma unroll
                    for (int i2 = 0; i2 < 4; ++i2) {
                        float4 c = tile[kb[j] + i2];
                        float d = fmaf(c.x, ax[j], fmaf(c.y, ay[j], fmaf(c.z, az[j], c.w)));
                        bool self = overlap && (kb[j] + i2 == sk[j]);
                        if (!found && !self && d == best[j]) { bi = kb[j] + i2; found = true; }
                    }
                    unsigned long long key =
                        ((unsigned long long)ford(best[j]) << 32) | (unsigned int)(lo + bi);
                    atomicMax(&g_best[ql[j]], ~key);      // max(~key) == min(key)
                }
            }
        }
    }
    gbar(&g_c2);

    // ---------- Phase D: strain + reduction (blocks 0..95) ----------
    if (b >= SBLK) return;

    int ncomp = g_ncomp;
    int slot = b * QB + tid;                              // compact query slot
    double qsq = 0.0;
    int cnt = 0;
    unsigned long long kp = g_best[slot];
    g_best[slot] = 0ULL;                                  // re-arm for next replay
    if (kp != 0ULL && slot < ncomp) {
        unsigned long long key = ~kp;
        float deff = finv((unsigned int)(key >> 32));
        int   nslot = (int)(unsigned int)(key & 0xffffffffu);
        int   i  = g_cidx[slot];
        int   nn = g_cidx[nslot];
        float wqx = new_xyz[3 * i + 0], wqy = new_xyz[3 * i + 1], wqz = new_xyz[3 * i + 2];
        float sqi = wqx * wqx + wqy * wqy + wqz * wqz;
        float mind2 = deff + sqi;                         // add back sq_i
        if (mind2 > 1e-16f) {                             // inside & (nn_d > 1e-8)
            cnt = 1;
            float wnx = new_xyz[3 * nn + 0], wny = new_xyz[3 * nn + 1], wnz = new_xyz[3 * nn + 2];
            float xi0 = xyz[3 * i + 0],  xi1 = xyz[3 * i + 1],  xi2 = xyz[3 * i + 2];
            float xn0 = xyz[3 * nn + 0], xn1 = xyz[3 * nn + 1], xn2 = xyz[3 * nn + 2];
            float du = (wnx - xn0) - (wqx - xi0);         // dm = motion[nn] - motion[i]
            float dv = (wny - xn1) - (wqy - xi1);
            float dw = (wnz - xn2) - (wqz - xi2);
            float dx = wnx - wqx + 1e-8f;
            float dy = wny - wqy + 1e-8f;
            float dz = wnz - wqz + 1e-8f;
            float e0 = du / dx, e1 = dv / dy, e2 = dw / dz;
            float e3 = (du / dy + dv / dx) * 0.5f;
            float e4 = (du / dz + dw / dx) * 0.5f;
            float e5 = (dw / dy + dv / dz) * 0.5f;
            float r0 = C.m[0] * e0 + C.m[1] * e1 + C.m[2] * e2;
            float r1 = C.m[3] * e0 + C.m[4] * e1 + C.m[5] * e2;
            float r2 = C.m[6] * e0 + C.m[7] * e1 + C.m[8] * e2;
            float qv = e0 * r0 + e1 * r1 + e2 * r2
                     + C.s * (e3 * e3 + e4 * e4 + e5 * e5);
            qsq = (double)qv * (double)qv;
        }
    }
    s_rd[tid] = qsq;
    s_ri[tid] = cnt;
    __syncthreads();
    #pragma unroll
    for (int o = QB / 2; o > 0; o >>= 1) {                // deterministic tree
        if (tid < o) { s_rd[tid] += s_rd[tid + o]; s_ri[tid] += s_ri[tid + o]; }
        __syncthreads();
    }
    if (tid == 0) {
        g_bsum[b] = s_rd[0];
        g_bcnt[b] = s_ri[0];
        __threadfence();
        unsigned int v = atomicAdd(&g_c3, 1u);
        s_last = ((v % SBLK) == SBLK - 1);                // monotone ticket
    }
    __syncthreads();

    if (s_last) {
        __threadfence();
        double s = 0.0; int c = 0;
        if (tid < SBLK) { s = g_bsum[tid]; c = g_bcnt[tid]; }
        s_rd[tid] = s; s_ri[tid] = c;
        __syncthreads();
        #pragma unroll
        for (int o = QB / 2; o > 0; o >>= 1) {
            if (tid < o) { s_rd[tid] += s_rd[tid + o]; s_ri[tid] += s_ri[tid + o]; }
            __syncthreads();
        }
        if (tid == 0)
            out[0] = (float)(sqrt(s_rd[0]) / (double)s_ri[0]);
    }
}

// ============================================================
extern "C" void kernel_launch(void* const* d_in, const int* in_sizes, int n_in,
                              void* d_out, int out_size) {
    const float* new_xyz = (const float*)d_in[0];
    const float* xyz     = (const float*)d_in[1];
    const float* gt_sdf  = (const float*)d_in[2];

    CMat C;
    {
        const double EP = 0.21, VP = 0.4;
        double A[3][3] = {{1.0/EP, -VP/EP, -VP/EP},
                          {-VP/EP, 1.0/EP, -VP/EP},
                          {-VP,    -VP,    1.0/EP}};
        double det = A[0][0]*(A[1][1]*A[2][2]-A[1][2]*A[2][1])
                   - A[0][1]*(A[1][0]*A[2][2]-A[1][2]*A[2][0])
                   + A[0][2]*(A[1][0]*A[2][1]-A[1][1]*A[2][0]);
        double inv[3][3];
        inv[0][0] = (A[1][1]*A[2][2]-A[1][2]*A[2][1])/det;
        inv[0][1] = (A[0][2]*A[2][1]-A[0][1]*A[2][2])/det;
        inv[0][2] = (A[0][1]*A[1][2]-A[0][2]*A[1][1])/det;
        inv[1][0] = (A[1][2]*A[2][0]-A[1][0]*A[2][2])/det;
        inv[1][1] = (A[0][0]*A[2][2]-A[0][2]*A[2][0])/det;
        inv[1][2] = (A[0][2]*A[1][0]-A[0][0]*A[1][2])/det;
        inv[2][0] = (A[1][0]*A[2][1]-A[1][1]*A[2][0])/det;
        inv[2][1] = (A[0][1]*A[2][0]-A[0][0]*A[2][1])/det;
        inv[2][2] = (A[0][0]*A[1][1]-A[0][1]*A[1][0])/det;
        for (int i = 0; i < 3; i++)
            for (int j = 0; j < 3; j++)
                C.m[i * 3 + j] = (float)inv[i][j];
        C.s = (float)(EP / (2.0 * (1.0 + VP)));
    }

    k_all<<<NB, QB>>>(new_xyz, xyz, gt_sdf, C, (float*)d_out);
}